// round 4
// baseline (speedup 1.0000x reference)
#include <cuda_runtime.h>
#include <math.h>

// Problem constants
#define BB   16
#define CC   512
#define NTOK 1024          // H*W = 32*32
#define GG   8
#define CPG  64            // C / G
#define EPSV 1e-5f
#define CN   (CC * NTOK)   // 524288 per-batch activation stride
#define SS   (NTOK * NTOK) // 1048576 per-batch attention stride

// Scratch (device globals — no allocations allowed)
__device__ float g_xn[BB * CN];   // normalized input
__device__ float g_q [BB * CN];
__device__ float g_k [BB * CN];
__device__ float g_v [BB * CN];
__device__ float g_s [BB * SS];   // S stored TRANSPOSED: g_s[b][j][i]
__device__ float g_o [BB * CN];

// ---------------------------------------------------------------------------
// GroupNorm: one block per (b, g). 64 channels x 1024 spatial = 65536 floats.
// ---------------------------------------------------------------------------
__global__ void __launch_bounds__(256)
groupnorm_kernel(const float* __restrict__ x,
                 const float* __restrict__ gamma,
                 const float* __restrict__ beta,
                 float* __restrict__ xn)
{
    const int b = blockIdx.x / GG;
    const int g = blockIdx.x % GG;
    const size_t base = (size_t)b * CN + (size_t)g * CPG * NTOK;
    const float4* __restrict__ x4 = (const float4*)(x + base);
    float4* __restrict__ o4 = (float4*)(xn + base);
    const int M4 = (CPG * NTOK) / 4;   // 16384 float4s
    const int t = threadIdx.x;

    float s = 0.f, ss = 0.f;
    for (int i = t; i < M4; i += 256) {
        float4 v = x4[i];
        s  += v.x + v.y + v.z + v.w;
        ss += v.x*v.x + v.y*v.y + v.z*v.z + v.w*v.w;
    }
    __shared__ float rs[256], rq[256];
    rs[t] = s; rq[t] = ss;
    __syncthreads();
    for (int o = 128; o > 0; o >>= 1) {
        if (t < o) { rs[t] += rs[t+o]; rq[t] += rq[t+o]; }
        __syncthreads();
    }
    const float cnt  = (float)(CPG * NTOK);
    const float mean = rs[0] / cnt;
    const float var  = rq[0] / cnt - mean * mean;
    const float inv  = rsqrtf(var + EPSV);

    for (int i = t; i < M4; i += 256) {
        const int c = g * CPG + i / (NTOK / 4);   // channel of this float4
        const float gm = gamma[c] * inv;
        const float bt = beta[c] - mean * gm;     // (v-mean)*inv*gamma + beta
        float4 v = x4[i];
        float4 r;
        r.x = v.x * gm + bt;  r.y = v.y * gm + bt;
        r.z = v.z * gm + bt;  r.w = v.w * gm + bt;
        o4[i] = r;
    }
}

// ---------------------------------------------------------------------------
// NN SGEMM: C[m][n] = sum_k A[m*K+k] * B[k*1024+n] (+bias[m]) (+resid[m][n])
// 128x128 tile, BK=8, 256 threads, 8x8 per-thread register tile.
// N dim is always 1024 (ldb = ldc = 1024). lda == K for all uses.
// ---------------------------------------------------------------------------
__global__ void __launch_bounds__(256)
gemm_nn_kernel(const float* __restrict__ Ag, const float* __restrict__ Bg,
               float* __restrict__ Cg,
               const float* __restrict__ bias,
               const float* __restrict__ resid,
               int K, long long sA, long long sB, long long sC)
{
    const int LDN = 1024;
    const int bz = blockIdx.z;
    const float* A = Ag + (size_t)bz * sA;
    const float* B = Bg + (size_t)bz * sB;
    float*       C = Cg + (size_t)bz * sC;
    const float* R = resid ? (resid + (size_t)bz * sC) : (const float*)0;

    const int m0 = blockIdx.y * 128;
    const int n0 = blockIdx.x * 128;

    __shared__ float As[8][128];
    __shared__ float Bs[8][128];

    const int tid = threadIdx.x;
    const int tn = (tid & 15) * 8;
    const int tm = (tid >> 4) * 8;

    float acc[8][8];
#pragma unroll
    for (int i = 0; i < 8; i++)
#pragma unroll
        for (int j = 0; j < 8; j++) acc[i][j] = 0.f;

    const int arow = tid >> 1;            // 0..127 (m within tile)
    const int acol = (tid & 1) * 4;       // 0 or 4 (k within tile)
    const int brow = tid >> 5;            // 0..7   (k within tile)
    const int bcol = (tid & 31) * 4;      // n within tile

    const float* Ap = A + (size_t)(m0 + arow) * K + acol;
    const float* Bp = B + (size_t)brow * LDN + n0 + bcol;

    for (int k0 = 0; k0 < K; k0 += 8) {
        float4 av = *(const float4*)Ap;
        float4 bv = *(const float4*)Bp;
        Ap += 8;
        Bp += (size_t)8 * LDN;
        As[acol + 0][arow] = av.x;
        As[acol + 1][arow] = av.y;
        As[acol + 2][arow] = av.z;
        As[acol + 3][arow] = av.w;
        *(float4*)&Bs[brow][bcol] = bv;
        __syncthreads();
#pragma unroll
        for (int kk = 0; kk < 8; kk++) {
            float4 a0 = *(const float4*)&As[kk][tm];
            float4 a1 = *(const float4*)&As[kk][tm + 4];
            float4 b0 = *(const float4*)&Bs[kk][tn];
            float4 b1 = *(const float4*)&Bs[kk][tn + 4];
            float ar[8] = {a0.x,a0.y,a0.z,a0.w,a1.x,a1.y,a1.z,a1.w};
            float br[8] = {b0.x,b0.y,b0.z,b0.w,b1.x,b1.y,b1.z,b1.w};
#pragma unroll
            for (int i = 0; i < 8; i++)
#pragma unroll
                for (int j = 0; j < 8; j++)
                    acc[i][j] = fmaf(ar[i], br[j], acc[i][j]);
        }
        __syncthreads();
    }

#pragma unroll
    for (int i = 0; i < 8; i++) {
        const int m = m0 + tm + i;
        const float bvv = bias ? bias[m] : 0.f;
#pragma unroll
        for (int j = 0; j < 8; j += 4) {
            const int n = n0 + tn + j;
            float4 r;
            r.x = acc[i][j+0] + bvv;
            r.y = acc[i][j+1] + bvv;
            r.z = acc[i][j+2] + bvv;
            r.w = acc[i][j+3] + bvv;
            if (R) {
                float4 rv = *(const float4*)&R[(size_t)m * LDN + n];
                r.x += rv.x; r.y += rv.y; r.z += rv.z; r.w += rv.w;
            }
            *(float4*)&C[(size_t)m * LDN + n] = r;
        }
    }
}

// ---------------------------------------------------------------------------
// TN SGEMM with scale: C[m][n] = scale * sum_k A[k*1024+m] * B[k*1024+n]
// Used for S^T[j][i] = scale * sum_c K[c][j] * Q[c][i].
// ---------------------------------------------------------------------------
__global__ void __launch_bounds__(256)
gemm_tn_scale_kernel(const float* __restrict__ Ag, const float* __restrict__ Bg,
                     float* __restrict__ Cg, float scale, int K,
                     long long sA, long long sB, long long sC)
{
    const int LDN = 1024;
    const int bz = blockIdx.z;
    const float* A = Ag + (size_t)bz * sA;
    const float* B = Bg + (size_t)bz * sB;
    float*       C = Cg + (size_t)bz * sC;

    const int m0 = blockIdx.y * 128;
    const int n0 = blockIdx.x * 128;

    __shared__ float As[8][128];
    __shared__ float Bs[8][128];

    const int tid = threadIdx.x;
    const int tn = (tid & 15) * 8;
    const int tm = (tid >> 4) * 8;

    float acc[8][8];
#pragma unroll
    for (int i = 0; i < 8; i++)
#pragma unroll
        for (int j = 0; j < 8; j++) acc[i][j] = 0.f;

    const int row = tid >> 5;            // k within tile, 0..7
    const int col = (tid & 31) * 4;      // m/n within tile

    const float* Ap = A + (size_t)row * LDN + m0 + col;
    const float* Bp = B + (size_t)row * LDN + n0 + col;

    for (int k0 = 0; k0 < K; k0 += 8) {
        float4 av = *(const float4*)Ap;
        float4 bv = *(const float4*)Bp;
        Ap += (size_t)8 * LDN;
        Bp += (size_t)8 * LDN;
        *(float4*)&As[row][col] = av;
        *(float4*)&Bs[row][col] = bv;
        __syncthreads();
#pragma unroll
        for (int kk = 0; kk < 8; kk++) {
            float4 a0 = *(const float4*)&As[kk][tm];
            float4 a1 = *(const float4*)&As[kk][tm + 4];
            float4 b0 = *(const float4*)&Bs[kk][tn];
            float4 b1 = *(const float4*)&Bs[kk][tn + 4];
            float ar[8] = {a0.x,a0.y,a0.z,a0.w,a1.x,a1.y,a1.z,a1.w};
            float br[8] = {b0.x,b0.y,b0.z,b0.w,b1.x,b1.y,b1.z,b1.w};
#pragma unroll
            for (int i = 0; i < 8; i++)
#pragma unroll
                for (int j = 0; j < 8; j++)
                    acc[i][j] = fmaf(ar[i], br[j], acc[i][j]);
        }
        __syncthreads();
    }

#pragma unroll
    for (int i = 0; i < 8; i++) {
        const int m = m0 + tm + i;
#pragma unroll
        for (int j = 0; j < 8; j += 4) {
            const int n = n0 + tn + j;
            float4 r;
            r.x = acc[i][j+0] * scale;
            r.y = acc[i][j+1] * scale;
            r.z = acc[i][j+2] * scale;
            r.w = acc[i][j+3] * scale;
            *(float4*)&C[(size_t)m * LDN + n] = r;
        }
    }
}

// ---------------------------------------------------------------------------
// Softmax over j for S^T layout [j][i]: thread t owns column i, loops over j.
// Fully coalesced (consecutive threads -> consecutive i).
// Pass 1: max. Pass 2: write exp(s-mx), accumulate sum. Pass 3: scale.
// ---------------------------------------------------------------------------
__global__ void __launch_bounds__(128)
softmax_kernel(float* __restrict__ s)
{
    const int b = blockIdx.y;
    const int i = blockIdx.x * 128 + threadIdx.x;
    float* S = s + (size_t)b * SS + i;

    float mx = -1e30f;
    for (int j = 0; j < NTOK; j++) mx = fmaxf(mx, S[(size_t)j * NTOK]);
    float sum = 0.f;
    for (int j = 0; j < NTOK; j++) {
        const size_t idx = (size_t)j * NTOK;
        const float e = __expf(S[idx] - mx);
        S[idx] = e;
        sum += e;
    }
    const float inv = 1.f / sum;
    for (int j = 0; j < NTOK; j++) {
        const size_t idx = (size_t)j * NTOK;
        S[idx] *= inv;
    }
}

// ---------------------------------------------------------------------------
// Launcher
// ---------------------------------------------------------------------------
extern "C" void kernel_launch(void* const* d_in, const int* in_sizes, int n_in,
                              void* d_out, int out_size)
{
    const float* x     = (const float*)d_in[0];
    const float* gamma = (const float*)d_in[1];
    const float* beta  = (const float*)d_in[2];
    const float* wq    = (const float*)d_in[3];
    const float* bq    = (const float*)d_in[4];
    const float* wk    = (const float*)d_in[5];
    const float* bk    = (const float*)d_in[6];
    const float* wv    = (const float*)d_in[7];
    const float* bv    = (const float*)d_in[8];
    const float* wp    = (const float*)d_in[9];
    const float* bp    = (const float*)d_in[10];
    float* out = (float*)d_out;

    float *xn, *q, *k, *v, *s, *o;
    cudaGetSymbolAddress((void**)&xn, g_xn);
    cudaGetSymbolAddress((void**)&q,  g_q);
    cudaGetSymbolAddress((void**)&k,  g_k);
    cudaGetSymbolAddress((void**)&v,  g_v);
    cudaGetSymbolAddress((void**)&s,  g_s);
    cudaGetSymbolAddress((void**)&o,  g_o);

    const float scale = 0.044194173824159216f;  // 1/sqrt(512)

    // 1) GroupNorm
    groupnorm_kernel<<<BB * GG, 256>>>(x, gamma, beta, xn);

    // 2) Q, K, V projections: M=512, N=1024, K=512 per batch
    dim3 gQKV(8, 4, BB);
    gemm_nn_kernel<<<gQKV, 256>>>(wq, xn, q, bq, 0, CC, 0, CN, CN);
    gemm_nn_kernel<<<gQKV, 256>>>(wk, xn, k, bk, 0, CC, 0, CN, CN);
    gemm_nn_kernel<<<gQKV, 256>>>(wv, xn, v, bv, 0, CC, 0, CN, CN);

    // 3) S^T[j][i] = scale * K^T Q : M=1024, N=1024, K=512
    dim3 gS(8, 8, BB);
    gemm_tn_scale_kernel<<<gS, 256>>>(k, q, s, scale, CC,
                                      (long long)CN, (long long)CN, (long long)SS);

    // 4) softmax over j (column direction of S^T), in place
    softmax_kernel<<<dim3(8, BB), 128>>>(s);

    // 5) O[c][i] = sum_j V[c][j] * P^T[j][i] : M=512, N=1024, K=1024
    gemm_nn_kernel<<<gQKV, 256>>>(v, s, o, 0, 0, NTOK,
                                  (long long)CN, (long long)SS, (long long)CN);

    // 6) proj + bias + residual -> out
    gemm_nn_kernel<<<gQKV, 256>>>(wp, o, out, bp, x, CC, 0, CN, CN);
}

// round 6
// speedup vs baseline: 3.0910x; 3.0910x over previous
#include <cuda_runtime.h>
#include <cstdint>
#include <math.h>

// ---------------------------------------------------------------------------
// Problem constants
// ---------------------------------------------------------------------------
#define BB   16
#define CC   512
#define NTOK 1024
#define GG   8
#define CPG  64
#define EPSV 1e-5f
#define CN   (CC * NTOK)     // 524288
#define SSTR (NTOK * NTOK)   // 1048576

// Scratch (device globals — no allocations allowed)
__device__ float g_xn[BB * CN];      // token-major normalized input [b][n][c], tf32-rounded
__device__ float g_q [BB * CN];      // [b][n][c] tf32-rounded
__device__ float g_k [BB * CN];      // [b][n][c] tf32-rounded
__device__ float g_v [BB * CN];      // channel-major [b][c][j] tf32-rounded
__device__ float g_s [BB * SSTR];    // S[b][i][j]; after softmax: P tf32-rounded
__device__ float g_o [BB * CN];      // [b][n][c] tf32-rounded
__device__ float g_w [4 * CC * CC];  // tf32-rounded wq, wk, wv, wp

// ---------------------------------------------------------------------------
// Helpers
// ---------------------------------------------------------------------------
__device__ __forceinline__ float to_tf32(float x) {
    uint32_t u;
    asm("cvt.rna.tf32.f32 %0, %1;" : "=r"(u) : "f"(x));
    return __uint_as_float(u);
}

__device__ __forceinline__ uint32_t smem_u32(const void* p) {
    uint32_t a;
    asm("{ .reg .u64 t; cvta.to.shared.u64 t, %1; cvt.u32.u64 %0, t; }"
        : "=r"(a) : "l"(p));
    return a;
}

#define CP_ASYNC16(saddr, gptr) \
    asm volatile("cp.async.cg.shared.global [%0], [%1], 16;" \
        :: "r"(saddr), "l"(gptr) : "memory")
#define CP_COMMIT() asm volatile("cp.async.commit_group;" ::: "memory")
#define CP_WAIT1()  asm volatile("cp.async.wait_group 1;" ::: "memory")
#define CP_WAIT0()  asm volatile("cp.async.wait_group 0;" ::: "memory")

// m16n8k8 tf32 MMA (sm_80 base ISA — valid on .target sm_100 plain)
__device__ __forceinline__ void mma16n8k8(float d[4],
                                          const uint32_t a[4],
                                          const uint32_t b[2]) {
    asm volatile(
        "mma.sync.aligned.m16n8k8.row.col.f32.tf32.tf32.f32 "
        "{%0,%1,%2,%3}, {%4,%5,%6,%7}, {%8,%9}, {%0,%1,%2,%3};"
        : "+f"(d[0]), "+f"(d[1]), "+f"(d[2]), "+f"(d[3])
        : "r"(a[0]), "r"(a[1]), "r"(a[2]), "r"(a[3]),
          "r"(b[0]), "r"(b[1]));
}

// ---------------------------------------------------------------------------
// Weight prep: round wq/wk/wv/wp to tf32 into g_w
// ---------------------------------------------------------------------------
__global__ void __launch_bounds__(256)
prep_weights_kernel(const float* __restrict__ wq, const float* __restrict__ wk,
                    const float* __restrict__ wv, const float* __restrict__ wp,
                    float* __restrict__ wout)
{
    const int i = blockIdx.x * 256 + threadIdx.x;  // float4 index, 65536 per matrix
    const float4* src[4] = { (const float4*)wq, (const float4*)wk,
                             (const float4*)wv, (const float4*)wp };
#pragma unroll
    for (int m = 0; m < 4; m++) {
        float4 v = src[m][i];
        v.x = to_tf32(v.x); v.y = to_tf32(v.y);
        v.z = to_tf32(v.z); v.w = to_tf32(v.w);
        ((float4*)(wout + m * CC * CC))[i] = v;
    }
}

// ---------------------------------------------------------------------------
// GroupNorm + transpose: x [b][c][n] -> xn token-major [b][n][c], tf32-rounded
// ---------------------------------------------------------------------------
__global__ void __launch_bounds__(256)
groupnorm_t_kernel(const float* __restrict__ x,
                   const float* __restrict__ gamma,
                   const float* __restrict__ beta,
                   float* __restrict__ xn)
{
    const int b = blockIdx.x / GG;
    const int g = blockIdx.x % GG;
    const size_t xbase = (size_t)b * CN + (size_t)g * CPG * NTOK;
    const int t = threadIdx.x;

    const float4* x4 = (const float4*)(x + xbase);
    const int M4 = (CPG * NTOK) / 4;   // 16384
    float s = 0.f, ss = 0.f;
    for (int i = t; i < M4; i += 256) {
        float4 v = x4[i];
        s  += v.x + v.y + v.z + v.w;
        ss += v.x*v.x + v.y*v.y + v.z*v.z + v.w*v.w;
    }
    __shared__ float rs[256], rq[256];
    rs[t] = s; rq[t] = ss;
    __syncthreads();
    for (int o = 128; o > 0; o >>= 1) {
        if (t < o) { rs[t] += rs[t+o]; rq[t] += rq[t+o]; }
        __syncthreads();
    }
    const float cnt  = (float)(CPG * NTOK);
    const float mean = rs[0] / cnt;
    const float var  = rq[0] / cnt - mean * mean;
    const float inv  = rsqrtf(var + EPSV);

    __shared__ float ts[64 * 65];
    const size_t obase = (size_t)b * CN + g * CPG;   // + n*CC + c
    for (int n0 = 0; n0 < NTOK; n0 += 64) {
        __syncthreads();
        for (int i = t; i < 64 * 16; i += 256) {
            const int c  = i >> 4;
            const int n4 = i & 15;
            const int cg = g * CPG + c;
            const float gm = gamma[cg] * inv;
            const float bt = beta[cg] - mean * gm;
            float4 v = *(const float4*)(x + (size_t)b * CN + (size_t)cg * NTOK + n0 + n4 * 4);
            ts[(n4*4 + 0) * 65 + c] = v.x * gm + bt;
            ts[(n4*4 + 1) * 65 + c] = v.y * gm + bt;
            ts[(n4*4 + 2) * 65 + c] = v.z * gm + bt;
            ts[(n4*4 + 3) * 65 + c] = v.w * gm + bt;
        }
        __syncthreads();
        for (int i = t; i < 64 * 16; i += 256) {
            const int n  = i >> 4;
            const int c4 = i & 15;
            float4 v;
            v.x = to_tf32(ts[n * 65 + c4*4 + 0]);
            v.y = to_tf32(ts[n * 65 + c4*4 + 1]);
            v.z = to_tf32(ts[n * 65 + c4*4 + 2]);
            v.w = to_tf32(ts[n * 65 + c4*4 + 3]);
            *(float4*)(xn + obase + (size_t)(n0 + n) * CC + c4 * 4) = v;
        }
    }
}

// ---------------------------------------------------------------------------
// Unified tensor-core tf32 GEMM via mma.sync:
//   D[m][n] = alpha * sum_k A[m][k]*B[n][k]
//             (+ biasM[m]) (+ biasN[n]) (+ resid[m][n]) (optional tf32 round)
// A: [M x Ktot] K-contiguous. B: [N x Ktot] K-contiguous. D row stride = ldc.
// CTA tile 128x128, BK=32, 8 warps (4x2), warp tile 32x64.
// cp.async double-buffered smem [128][36] (conflict-free fragment LDS).
// ---------------------------------------------------------------------------
#define BKT 32
#define LDT 36   // BK + 4 pad

__global__ void __launch_bounds__(256)
gemm_mma(const float* __restrict__ Ag, const float* __restrict__ Bg,
         float* __restrict__ Dg, int Ktot, int ldc,
         long long sA, long long sB, long long sD,
         float alpha,
         const float* __restrict__ biasM, const float* __restrict__ biasN,
         const float* __restrict__ resid, int round_out)
{
    extern __shared__ float sm[];
    float* As[2] = { sm,               sm + 2 * 128 * LDT };
    float* Bs[2] = { sm + 128 * LDT,   sm + 3 * 128 * LDT };

    const int tid  = threadIdx.x;
    const int lane = tid & 31;
    const int wid  = tid >> 5;
    const int wm   = (wid & 3) * 32;   // warp m offset in tile
    const int wn   = (wid >> 2) * 64;  // warp n offset in tile
    const int gtr  = lane >> 2;        // groupID 0..7
    const int t4   = lane & 3;         // threadID-in-group 0..3

    const int bz = blockIdx.z;
    const float* A = Ag + (size_t)bz * sA;
    const float* B = Bg + (size_t)bz * sB;
    float*       D = Dg + (size_t)bz * sD;
    const int m0 = blockIdx.y * 128;
    const int n0 = blockIdx.x * 128;

    float acc[2][8][4];
#pragma unroll
    for (int i = 0; i < 2; i++)
#pragma unroll
        for (int j = 0; j < 8; j++)
#pragma unroll
            for (int q = 0; q < 4; q++) acc[i][j][q] = 0.f;

    const int NIT = Ktot / BKT;

    // producer: 256 threads x 4 iters cover 1024 float4 per tile
    const int prow = tid >> 1;           // base row pattern helper (unused)
    (void)prow;

    auto issue_loads = [&](int it, int buf) {
        const float* Asrc = A + (size_t)m0 * Ktot + it * BKT;
        const float* Bsrc = B + (size_t)n0 * Ktot + it * BKT;
        uint32_t aBase = smem_u32(As[buf]);
        uint32_t bBase = smem_u32(Bs[buf]);
#pragma unroll
        for (int r = 0; r < 4; r++) {
            const int idx = tid + r * 256;     // 0..1023
            const int row = idx >> 3;          // 0..127
            const int q   = idx & 7;           // float4 within 32-K row
            CP_ASYNC16(aBase + (uint32_t)(row * LDT + q * 4) * 4u,
                       Asrc + (size_t)row * Ktot + q * 4);
            CP_ASYNC16(bBase + (uint32_t)(row * LDT + q * 4) * 4u,
                       Bsrc + (size_t)row * Ktot + q * 4);
        }
        CP_COMMIT();
    };

    issue_loads(0, 0);

    for (int it = 0; it < NIT; ++it) {
        const int buf = it & 1;
        if (it + 1 < NIT) {
            issue_loads(it + 1, buf ^ 1);
            CP_WAIT1();
        } else {
            CP_WAIT0();
        }
        __syncthreads();

        const float* Ab = As[buf];
        const float* Bb = Bs[buf];
#pragma unroll
        for (int ks = 0; ks < 4; ++ks) {
            const int k0 = ks * 8;
            uint32_t af[2][4];
#pragma unroll
            for (int ma = 0; ma < 2; ++ma) {
                const int r0 = wm + ma * 16 + gtr;
                af[ma][0] = __float_as_uint(Ab[(r0    ) * LDT + k0 + t4    ]);
                af[ma][1] = __float_as_uint(Ab[(r0 + 8) * LDT + k0 + t4    ]);
                af[ma][2] = __float_as_uint(Ab[(r0    ) * LDT + k0 + t4 + 4]);
                af[ma][3] = __float_as_uint(Ab[(r0 + 8) * LDT + k0 + t4 + 4]);
            }
            uint32_t bf[8][2];
#pragma unroll
            for (int nb = 0; nb < 8; ++nb) {
                const int c0 = wn + nb * 8 + gtr;
                bf[nb][0] = __float_as_uint(Bb[c0 * LDT + k0 + t4    ]);
                bf[nb][1] = __float_as_uint(Bb[c0 * LDT + k0 + t4 + 4]);
            }
#pragma unroll
            for (int ma = 0; ma < 2; ++ma)
#pragma unroll
                for (int nb = 0; nb < 8; ++nb)
                    mma16n8k8(acc[ma][nb], af[ma], bf[nb]);
        }
        __syncthreads();
    }

    // Epilogue: thread owns rows (wm+ma*16+gtr, +8), cols wn+nb*8+2*t4 (+1)
    const float* Rb = resid ? (resid + (size_t)bz * sD) : (const float*)0;
#pragma unroll
    for (int ma = 0; ma < 2; ++ma) {
        const int mrow0 = m0 + wm + ma * 16 + gtr;
        const int mrow1 = mrow0 + 8;
        const float bm0 = biasM ? biasM[mrow0] : 0.f;
        const float bm1 = biasM ? biasM[mrow1] : 0.f;
#pragma unroll
        for (int nb = 0; nb < 8; ++nb) {
            const int col = n0 + wn + nb * 8 + 2 * t4;
            float d0 = acc[ma][nb][0] * alpha + bm0;
            float d1 = acc[ma][nb][1] * alpha + bm0;
            float d2 = acc[ma][nb][2] * alpha + bm1;
            float d3 = acc[ma][nb][3] * alpha + bm1;
            if (biasN) {
                const float b0 = biasN[col], b1 = biasN[col + 1];
                d0 += b0; d1 += b1; d2 += b0; d3 += b1;
            }
            if (Rb) {
                const float2 r0 = *(const float2*)&Rb[(size_t)mrow0 * ldc + col];
                const float2 r1 = *(const float2*)&Rb[(size_t)mrow1 * ldc + col];
                d0 += r0.x; d1 += r0.y; d2 += r1.x; d3 += r1.y;
            }
            if (round_out) {
                d0 = to_tf32(d0); d1 = to_tf32(d1);
                d2 = to_tf32(d2); d3 = to_tf32(d3);
            }
            float2 o0 = { d0, d1 };
            float2 o1 = { d2, d3 };
            *(float2*)&D[(size_t)mrow0 * ldc + col] = o0;
            *(float2*)&D[(size_t)mrow1 * ldc + col] = o1;
        }
    }
}

// ---------------------------------------------------------------------------
// Row softmax: one 256-thread block per row (1024 floats). Writes P tf32.
// ---------------------------------------------------------------------------
__global__ void __launch_bounds__(256)
softmax_rows(float* __restrict__ S)
{
    float4* R = (float4*)(S + (size_t)blockIdx.x * NTOK);
    const int t = threadIdx.x;
    float4 v = R[t];

    float mx = fmaxf(fmaxf(v.x, v.y), fmaxf(v.z, v.w));
#pragma unroll
    for (int o = 16; o; o >>= 1) mx = fmaxf(mx, __shfl_xor_sync(0xffffffffu, mx, o));
    __shared__ float smax[8], ssum[8];
    if ((t & 31) == 0) smax[t >> 5] = mx;
    __syncthreads();
    float mm = smax[0];
#pragma unroll
    for (int i = 1; i < 8; ++i) mm = fmaxf(mm, smax[i]);

    float4 e;
    e.x = __expf(v.x - mm); e.y = __expf(v.y - mm);
    e.z = __expf(v.z - mm); e.w = __expf(v.w - mm);
    float su = e.x + e.y + e.z + e.w;
#pragma unroll
    for (int o = 16; o; o >>= 1) su += __shfl_xor_sync(0xffffffffu, su, o);
    if ((t & 31) == 0) ssum[t >> 5] = su;
    __syncthreads();
    float tot = 0.f;
#pragma unroll
    for (int i = 0; i < 8; ++i) tot += ssum[i];
    const float inv = 1.f / tot;

    float4 p;
    p.x = to_tf32(e.x * inv); p.y = to_tf32(e.y * inv);
    p.z = to_tf32(e.z * inv); p.w = to_tf32(e.w * inv);
    R[t] = p;
}

// ---------------------------------------------------------------------------
// Launcher
// ---------------------------------------------------------------------------
extern "C" void kernel_launch(void* const* d_in, const int* in_sizes, int n_in,
                              void* d_out, int out_size)
{
    const float* x     = (const float*)d_in[0];
    const float* gamma = (const float*)d_in[1];
    const float* beta  = (const float*)d_in[2];
    const float* wq    = (const float*)d_in[3];
    const float* bq    = (const float*)d_in[4];
    const float* wk    = (const float*)d_in[5];
    const float* bk    = (const float*)d_in[6];
    const float* wv    = (const float*)d_in[7];
    const float* bv    = (const float*)d_in[8];
    const float* wp    = (const float*)d_in[9];
    const float* bp    = (const float*)d_in[10];
    float* out = (float*)d_out;

    float *xn, *q, *k, *v, *s, *o, *w;
    cudaGetSymbolAddress((void**)&xn, g_xn);
    cudaGetSymbolAddress((void**)&q,  g_q);
    cudaGetSymbolAddress((void**)&k,  g_k);
    cudaGetSymbolAddress((void**)&v,  g_v);
    cudaGetSymbolAddress((void**)&s,  g_s);
    cudaGetSymbolAddress((void**)&o,  g_o);
    cudaGetSymbolAddress((void**)&w,  g_w);
    const float* wrq = w + 0 * CC * CC;
    const float* wrk = w + 1 * CC * CC;
    const float* wrv = w + 2 * CC * CC;
    const float* wrp = w + 3 * CC * CC;

    const int SMEM_DYN = 4 * 128 * LDT * 4;   // 73728 B
    static int attr_set = 0;
    cudaFuncSetAttribute(gemm_mma, cudaFuncAttributeMaxDynamicSharedMemorySize, SMEM_DYN);
    (void)attr_set;

    const float scale = 0.044194173824159216f;  // 1/sqrt(512)

    // 0) round weights to tf32
    prep_weights_kernel<<<256, 256>>>(wq, wk, wv, wp, w);

    // 1) GroupNorm -> token-major xn (tf32)
    groupnorm_t_kernel<<<BB * GG, 256>>>(x, gamma, beta, xn);

    // 2) Q[n][o], K[n][o]:  M=1024(tokens) N=512(out-ch) K=512
    gemm_mma<<<dim3(4, 8, BB), 256, SMEM_DYN>>>(xn, wrq, q, CC, CC,
        (long long)CN, 0LL, (long long)CN, 1.f, 0, bq, 0, 1);
    gemm_mma<<<dim3(4, 8, BB), 256, SMEM_DYN>>>(xn, wrk, k, CC, CC,
        (long long)CN, 0LL, (long long)CN, 1.f, 0, bk, 0, 1);

    // 3) V[c][j]: M=512(ch) N=1024(tokens) K=512 (channel-major out)
    gemm_mma<<<dim3(8, 4, BB), 256, SMEM_DYN>>>(wrv, xn, v, CC, NTOK,
        0LL, (long long)CN, (long long)CN, 1.f, bv, 0, 0, 1);

    // 4) S[i][j] = scale * Q[i][:].K[j][:]  M=N=1024 K=512
    gemm_mma<<<dim3(8, 8, BB), 256, SMEM_DYN>>>(q, k, s, CC, NTOK,
        (long long)CN, (long long)CN, (long long)SSTR, scale, 0, 0, 0, 0);

    // 5) row softmax (writes tf32 P)
    softmax_rows<<<BB * NTOK, 256>>>(s);

    // 6) O[i][c] = P[i][:].V[c][:]  M=1024 N=512 K=1024
    gemm_mma<<<dim3(4, 8, BB), 256, SMEM_DYN>>>(s, v, o, NTOK, CC,
        (long long)SSTR, (long long)CN, (long long)CN, 1.f, 0, 0, 0, 1);

    // 7) out[c][n] = wp[c][:].O[n][:] + bp[c] + x[c][n]  M=512 N=1024 K=512
    gemm_mma<<<dim3(8, 4, BB), 256, SMEM_DYN>>>(wrp, o, out, CC, NTOK,
        0LL, (long long)CN, (long long)CN, 1.f, bp, 0, x, 0);
}

// round 7
// speedup vs baseline: 5.1442x; 1.6642x over previous
#include <cuda_runtime.h>
#include <cuda_bf16.h>
#include <cstdint>
#include <math.h>

// ---------------------------------------------------------------------------
// Problem constants
// ---------------------------------------------------------------------------
#define BB   16
#define CC   512
#define NTOK 1024
#define GG   8
#define CPG  64
#define EPSV 1e-5f
#define CN   (CC * NTOK)     // 524288
#define SSTR (NTOK * NTOK)   // 1048576

typedef __nv_bfloat16 bf16;

// Scratch (device globals — no allocations allowed)
__device__ bf16  g_xn[BB * CN];      // token-major normalized input [b][n][c]
__device__ bf16  g_q [BB * CN];      // [b][n][c]
__device__ bf16  g_k [BB * CN];      // [b][n][c]
__device__ bf16  g_v [BB * CN];      // channel-major [b][c][j]
__device__ float g_s [BB * SSTR];    // S[b][i][j] fp32 (pre-softmax)
__device__ bf16  g_p [BB * SSTR];    // P[b][i][j] bf16 (post-softmax)
__device__ bf16  g_o [BB * CN];      // [b][n][c]
__device__ bf16  g_w [4 * CC * CC];  // bf16 wq, wk, wv, wp

// ---------------------------------------------------------------------------
// Helpers
// ---------------------------------------------------------------------------
__device__ __forceinline__ uint32_t smem_u32(const void* p) {
    uint32_t a;
    asm("{ .reg .u64 t; cvta.to.shared.u64 t, %1; cvt.u32.u64 %0, t; }"
        : "=r"(a) : "l"(p));
    return a;
}

__device__ __forceinline__ uint32_t pack_bf2(float lo, float hi) {
    __nv_bfloat162 h = __floats2bfloat162_rn(lo, hi);
    return *(uint32_t*)&h;
}

#define CP_ASYNC16(saddr, gptr) \
    asm volatile("cp.async.cg.shared.global [%0], [%1], 16;" \
        :: "r"(saddr), "l"(gptr) : "memory")
#define CP_COMMIT() asm volatile("cp.async.commit_group;" ::: "memory")
#define CP_WAIT1()  asm volatile("cp.async.wait_group 1;" ::: "memory")
#define CP_WAIT0()  asm volatile("cp.async.wait_group 0;" ::: "memory")

// m16n8k16 bf16 MMA (sm_80 base ISA)
__device__ __forceinline__ void mma16n8k16(float d[4],
                                           const uint32_t a[4],
                                           const uint32_t b[2]) {
    asm volatile(
        "mma.sync.aligned.m16n8k16.row.col.f32.bf16.bf16.f32 "
        "{%0,%1,%2,%3}, {%4,%5,%6,%7}, {%8,%9}, {%0,%1,%2,%3};"
        : "+f"(d[0]), "+f"(d[1]), "+f"(d[2]), "+f"(d[3])
        : "r"(a[0]), "r"(a[1]), "r"(a[2]), "r"(a[3]),
          "r"(b[0]), "r"(b[1]));
}

// ---------------------------------------------------------------------------
// Weight prep: fp32 wq/wk/wv/wp -> bf16 g_w
// ---------------------------------------------------------------------------
__global__ void __launch_bounds__(256)
prep_weights_kernel(const float* __restrict__ wq, const float* __restrict__ wk,
                    const float* __restrict__ wv, const float* __restrict__ wp,
                    bf16* __restrict__ wout)
{
    const int i = blockIdx.x * 256 + threadIdx.x;  // float4 index, 65536 per matrix
    const float4* src[4] = { (const float4*)wq, (const float4*)wk,
                             (const float4*)wv, (const float4*)wp };
#pragma unroll
    for (int m = 0; m < 4; m++) {
        float4 v = src[m][i];
        uint2 o;
        o.x = pack_bf2(v.x, v.y);
        o.y = pack_bf2(v.z, v.w);
        ((uint2*)(wout + m * CC * CC))[i] = o;
    }
}

// ---------------------------------------------------------------------------
// GroupNorm + transpose: x [b][c][n] fp32 -> xn token-major [b][n][c] bf16
// ---------------------------------------------------------------------------
__global__ void __launch_bounds__(256)
groupnorm_t_kernel(const float* __restrict__ x,
                   const float* __restrict__ gamma,
                   const float* __restrict__ beta,
                   bf16* __restrict__ xn)
{
    const int b = blockIdx.x / GG;
    const int g = blockIdx.x % GG;
    const size_t xbase = (size_t)b * CN + (size_t)g * CPG * NTOK;
    const int t = threadIdx.x;

    const float4* x4 = (const float4*)(x + xbase);
    const int M4 = (CPG * NTOK) / 4;   // 16384
    float s = 0.f, ss = 0.f;
    for (int i = t; i < M4; i += 256) {
        float4 v = x4[i];
        s  += v.x + v.y + v.z + v.w;
        ss += v.x*v.x + v.y*v.y + v.z*v.z + v.w*v.w;
    }
    __shared__ float rs[256], rq[256];
    rs[t] = s; rq[t] = ss;
    __syncthreads();
    for (int o = 128; o > 0; o >>= 1) {
        if (t < o) { rs[t] += rs[t+o]; rq[t] += rq[t+o]; }
        __syncthreads();
    }
    const float cnt  = (float)(CPG * NTOK);
    const float mean = rs[0] / cnt;
    const float var  = rq[0] / cnt - mean * mean;
    const float inv  = rsqrtf(var + EPSV);

    __shared__ float ts[64 * 65];
    const size_t obase = (size_t)b * CN + g * CPG;   // + n*CC + c
    for (int n0 = 0; n0 < NTOK; n0 += 64) {
        __syncthreads();
        for (int i = t; i < 64 * 16; i += 256) {
            const int c  = i >> 4;
            const int n4 = i & 15;
            const int cg = g * CPG + c;
            const float gm = gamma[cg] * inv;
            const float bt = beta[cg] - mean * gm;
            float4 v = *(const float4*)(x + (size_t)b * CN + (size_t)cg * NTOK + n0 + n4 * 4);
            ts[(n4*4 + 0) * 65 + c] = v.x * gm + bt;
            ts[(n4*4 + 1) * 65 + c] = v.y * gm + bt;
            ts[(n4*4 + 2) * 65 + c] = v.z * gm + bt;
            ts[(n4*4 + 3) * 65 + c] = v.w * gm + bt;
        }
        __syncthreads();
        for (int i = t; i < 64 * 16; i += 256) {
            const int n  = i >> 4;
            const int c4 = i & 15;
            uint2 o;
            o.x = pack_bf2(ts[n * 65 + c4*4 + 0], ts[n * 65 + c4*4 + 1]);
            o.y = pack_bf2(ts[n * 65 + c4*4 + 2], ts[n * 65 + c4*4 + 3]);
            *(uint2*)(xn + obase + (size_t)(n0 + n) * CC + c4 * 4) = o;
        }
    }
}

// ---------------------------------------------------------------------------
// Unified bf16 tensor-core GEMM via mma.sync m16n8k16:
//   D[m][n] = alpha * sum_k A[m][k]*B[n][k]
//             (+ biasM[m]) (+ biasN[n]) (+ resid[m][n])
// A: [M x Ktot] bf16 K-contiguous. B: [N x Ktot] bf16 K-contiguous.
// D: fp32 (out_bf16=0) or bf16 (out_bf16=1), row stride ldc.
// CTA tile 128x128, BK=64, 8 warps (4x2), warp tile 32x64.
// cp.async double-buffered smem [128][72] bf16 (conflict-free fragment LDS).
// ---------------------------------------------------------------------------
#define BKT 64
#define LDT 72   // BK + 8 pad (bf16 elements; 144 bytes/row)

__global__ void __launch_bounds__(256)
gemm_bf(const bf16* __restrict__ Ag, const bf16* __restrict__ Bg,
        void* __restrict__ Dg, int Ktot, int ldc,
        long long sA, long long sB, long long sD,
        float alpha,
        const float* __restrict__ biasM, const float* __restrict__ biasN,
        const float* __restrict__ resid, int out_bf16)
{
    extern __shared__ bf16 sm[];
    bf16* As[2] = { sm,               sm + 2 * 128 * LDT };
    bf16* Bs[2] = { sm + 128 * LDT,   sm + 3 * 128 * LDT };

    const int tid  = threadIdx.x;
    const int lane = tid & 31;
    const int wid  = tid >> 5;
    const int wm   = (wid & 3) * 32;   // warp m offset in tile
    const int wn   = (wid >> 2) * 64;  // warp n offset in tile
    const int gtr  = lane >> 2;        // groupID 0..7
    const int t4   = lane & 3;         // threadID-in-group 0..3

    const int bz = blockIdx.z;
    const bf16* A = Ag + (size_t)bz * sA;
    const bf16* B = Bg + (size_t)bz * sB;
    const int m0 = blockIdx.y * 128;
    const int n0 = blockIdx.x * 128;

    float acc[2][8][4];
#pragma unroll
    for (int i = 0; i < 2; i++)
#pragma unroll
        for (int j = 0; j < 8; j++)
#pragma unroll
            for (int q = 0; q < 4; q++) acc[i][j][q] = 0.f;

    const int NIT = Ktot / BKT;

    auto issue_loads = [&](int it, int buf) {
        const bf16* Asrc = A + (size_t)m0 * Ktot + it * BKT;
        const bf16* Bsrc = B + (size_t)n0 * Ktot + it * BKT;
        uint32_t aBase = smem_u32(As[buf]);
        uint32_t bBase = smem_u32(Bs[buf]);
        // per tile: 128 rows x 64 bf16 = 128 rows x 8 float4-chunks = 1024 chunks
#pragma unroll
        for (int r = 0; r < 4; r++) {
            const int idx = tid + r * 256;     // 0..1023
            const int row = idx >> 3;          // 0..127
            const int q   = idx & 7;           // 16B chunk within row
            CP_ASYNC16(aBase + (uint32_t)(row * LDT + q * 8) * 2u,
                       Asrc + (size_t)row * Ktot + q * 8);
            CP_ASYNC16(bBase + (uint32_t)(row * LDT + q * 8) * 2u,
                       Bsrc + (size_t)row * Ktot + q * 8);
        }
        CP_COMMIT();
    };

    issue_loads(0, 0);

    for (int it = 0; it < NIT; ++it) {
        const int buf = it & 1;
        if (it + 1 < NIT) {
            issue_loads(it + 1, buf ^ 1);
            CP_WAIT1();
        } else {
            CP_WAIT0();
        }
        __syncthreads();

        const bf16* Ab = As[buf];
        const bf16* Bb = Bs[buf];
#pragma unroll
        for (int ks = 0; ks < 4; ++ks) {
            const int k0 = ks * 16;
            uint32_t af[2][4];
#pragma unroll
            for (int ma = 0; ma < 2; ++ma) {
                const int r0 = wm + ma * 16 + gtr;
                af[ma][0] = *(const uint32_t*)&Ab[(r0    ) * LDT + k0 + 2*t4    ];
                af[ma][1] = *(const uint32_t*)&Ab[(r0 + 8) * LDT + k0 + 2*t4    ];
                af[ma][2] = *(const uint32_t*)&Ab[(r0    ) * LDT + k0 + 2*t4 + 8];
                af[ma][3] = *(const uint32_t*)&Ab[(r0 + 8) * LDT + k0 + 2*t4 + 8];
            }
            uint32_t bfr[8][2];
#pragma unroll
            for (int nb = 0; nb < 8; ++nb) {
                const int c0 = wn + nb * 8 + gtr;
                bfr[nb][0] = *(const uint32_t*)&Bb[c0 * LDT + k0 + 2*t4    ];
                bfr[nb][1] = *(const uint32_t*)&Bb[c0 * LDT + k0 + 2*t4 + 8];
            }
#pragma unroll
            for (int ma = 0; ma < 2; ++ma)
#pragma unroll
                for (int nb = 0; nb < 8; ++nb)
                    mma16n8k16(acc[ma][nb], af[ma], bfr[nb]);
        }
        __syncthreads();
    }

    // Epilogue: thread owns rows (wm+ma*16+gtr, +8), cols wn+nb*8+2*t4 (+1)
    const float* Rb = resid ? (resid + (size_t)bz * sD) : (const float*)0;
    float* Df = (float*)Dg + (size_t)bz * sD;
    bf16*  Dh = (bf16*)Dg + (size_t)bz * sD;
#pragma unroll
    for (int ma = 0; ma < 2; ++ma) {
        const int mrow0 = m0 + wm + ma * 16 + gtr;
        const int mrow1 = mrow0 + 8;
        const float bm0 = biasM ? biasM[mrow0] : 0.f;
        const float bm1 = biasM ? biasM[mrow1] : 0.f;
#pragma unroll
        for (int nb = 0; nb < 8; ++nb) {
            const int col = n0 + wn + nb * 8 + 2 * t4;
            float d0 = acc[ma][nb][0] * alpha + bm0;
            float d1 = acc[ma][nb][1] * alpha + bm0;
            float d2 = acc[ma][nb][2] * alpha + bm1;
            float d3 = acc[ma][nb][3] * alpha + bm1;
            if (biasN) {
                const float b0 = biasN[col], b1 = biasN[col + 1];
                d0 += b0; d1 += b1; d2 += b0; d3 += b1;
            }
            if (Rb) {
                const float2 r0 = *(const float2*)&Rb[(size_t)mrow0 * ldc + col];
                const float2 r1 = *(const float2*)&Rb[(size_t)mrow1 * ldc + col];
                d0 += r0.x; d1 += r0.y; d2 += r1.x; d3 += r1.y;
            }
            if (out_bf16) {
                *(uint32_t*)&Dh[(size_t)mrow0 * ldc + col] = pack_bf2(d0, d1);
                *(uint32_t*)&Dh[(size_t)mrow1 * ldc + col] = pack_bf2(d2, d3);
            } else {
                float2 o0 = { d0, d1 };
                float2 o1 = { d2, d3 };
                *(float2*)&Df[(size_t)mrow0 * ldc + col] = o0;
                *(float2*)&Df[(size_t)mrow1 * ldc + col] = o1;
            }
        }
    }
}

// ---------------------------------------------------------------------------
// Row softmax: one 256-thread block per row. fp32 S in, bf16 P out.
// ---------------------------------------------------------------------------
__global__ void __launch_bounds__(256)
softmax_rows(const float* __restrict__ S, bf16* __restrict__ P)
{
    const float4* R = (const float4*)(S + (size_t)blockIdx.x * NTOK);
    const int t = threadIdx.x;
    float4 v = R[t];

    float mx = fmaxf(fmaxf(v.x, v.y), fmaxf(v.z, v.w));
#pragma unroll
    for (int o = 16; o; o >>= 1) mx = fmaxf(mx, __shfl_xor_sync(0xffffffffu, mx, o));
    __shared__ float smax[8], ssum[8];
    if ((t & 31) == 0) smax[t >> 5] = mx;
    __syncthreads();
    float mm = smax[0];
#pragma unroll
    for (int i = 1; i < 8; ++i) mm = fmaxf(mm, smax[i]);

    float4 e;
    e.x = __expf(v.x - mm); e.y = __expf(v.y - mm);
    e.z = __expf(v.z - mm); e.w = __expf(v.w - mm);
    float su = e.x + e.y + e.z + e.w;
#pragma unroll
    for (int o = 16; o; o >>= 1) su += __shfl_xor_sync(0xffffffffu, su, o);
    if ((t & 31) == 0) ssum[t >> 5] = su;
    __syncthreads();
    float tot = 0.f;
#pragma unroll
    for (int i = 0; i < 8; ++i) tot += ssum[i];
    const float inv = 1.f / tot;

    uint2 o;
    o.x = pack_bf2(e.x * inv, e.y * inv);
    o.y = pack_bf2(e.z * inv, e.w * inv);
    *(uint2*)(P + (size_t)blockIdx.x * NTOK + t * 4) = o;
}

// ---------------------------------------------------------------------------
// Launcher
// ---------------------------------------------------------------------------
extern "C" void kernel_launch(void* const* d_in, const int* in_sizes, int n_in,
                              void* d_out, int out_size)
{
    const float* x     = (const float*)d_in[0];
    const float* gamma = (const float*)d_in[1];
    const float* beta  = (const float*)d_in[2];
    const float* wq    = (const float*)d_in[3];
    const float* bq    = (const float*)d_in[4];
    const float* wk    = (const float*)d_in[5];
    const float* bk    = (const float*)d_in[6];
    const float* wv    = (const float*)d_in[7];
    const float* bv    = (const float*)d_in[8];
    const float* wp    = (const float*)d_in[9];
    const float* bp    = (const float*)d_in[10];
    float* out = (float*)d_out;

    bf16 *xn, *q, *k, *v, *p, *o, *w;
    float *s;
    cudaGetSymbolAddress((void**)&xn, g_xn);
    cudaGetSymbolAddress((void**)&q,  g_q);
    cudaGetSymbolAddress((void**)&k,  g_k);
    cudaGetSymbolAddress((void**)&v,  g_v);
    cudaGetSymbolAddress((void**)&s,  g_s);
    cudaGetSymbolAddress((void**)&p,  g_p);
    cudaGetSymbolAddress((void**)&o,  g_o);
    cudaGetSymbolAddress((void**)&w,  g_w);
    const bf16* wrq = w + 0 * CC * CC;
    const bf16* wrk = w + 1 * CC * CC;
    const bf16* wrv = w + 2 * CC * CC;
    const bf16* wrp = w + 3 * CC * CC;

    const int SMEM_DYN = 4 * 128 * LDT * 2;   // 73728 B
    cudaFuncSetAttribute(gemm_bf, cudaFuncAttributeMaxDynamicSharedMemorySize, SMEM_DYN);

    const float scale = 0.044194173824159216f;  // 1/sqrt(512)

    // 0) weights -> bf16
    prep_weights_kernel<<<256, 256>>>(wq, wk, wv, wp, w);

    // 1) GroupNorm -> token-major bf16 xn
    groupnorm_t_kernel<<<BB * GG, 256>>>(x, gamma, beta, xn);

    // 2) Q[n][o], K[n][o]:  M=1024(tokens) N=512(out-ch) K=512
    gemm_bf<<<dim3(4, 8, BB), 256, SMEM_DYN>>>(xn, wrq, q, CC, CC,
        (long long)CN, 0LL, (long long)CN, 1.f, 0, bq, 0, 1);
    gemm_bf<<<dim3(4, 8, BB), 256, SMEM_DYN>>>(xn, wrk, k, CC, CC,
        (long long)CN, 0LL, (long long)CN, 1.f, 0, bk, 0, 1);

    // 3) V[c][j]: M=512(ch) N=1024(tokens) K=512 (channel-major out)
    gemm_bf<<<dim3(8, 4, BB), 256, SMEM_DYN>>>(wrv, xn, v, CC, NTOK,
        0LL, (long long)CN, (long long)CN, 1.f, bv, 0, 0, 1);

    // 4) S[i][j] = scale * Q[i][:].K[j][:]  M=N=1024 K=512 (fp32 out)
    gemm_bf<<<dim3(8, 8, BB), 256, SMEM_DYN>>>(q, k, s, CC, NTOK,
        (long long)CN, (long long)CN, (long long)SSTR, scale, 0, 0, 0, 0);

    // 5) row softmax fp32 -> bf16 P
    softmax_rows<<<BB * NTOK, 256>>>(s, p);

    // 6) O[i][c] = P[i][:].V[c][:]  M=1024 N=512 K=1024
    gemm_bf<<<dim3(4, 8, BB), 256, SMEM_DYN>>>(p, v, o, NTOK, CC,
        (long long)SSTR, (long long)CN, (long long)CN, 1.f, 0, 0, 0, 1);

    // 7) out[c][n] = wp[c][:].O[n][:] + bp[c] + x[c][n]  M=512 N=1024 K=512 (fp32+resid)
    gemm_bf<<<dim3(8, 4, BB), 256, SMEM_DYN>>>(wrp, o, out, CC, NTOK,
        0LL, (long long)CN, (long long)CN, 1.f, bp, 0, x, 0);
}

// round 9
// speedup vs baseline: 5.5711x; 1.0830x over previous
#include <cuda_runtime.h>
#include <cuda_bf16.h>
#include <cstdint>
#include <math.h>

// ---------------------------------------------------------------------------
// Problem constants
// ---------------------------------------------------------------------------
#define BB   16
#define CC   512
#define NTOK 1024
#define GG   8
#define CPG  64
#define EPSV 1e-5f
#define CN   (CC * NTOK)     // 524288
#define SSTR (NTOK * NTOK)   // 1048576

typedef __nv_bfloat16 bf16;

// Scratch (device globals — no allocations allowed)
__device__ bf16  g_xn[BB * CN];      // token-major normalized input [b][n][c]
__device__ bf16  g_q [BB * CN];      // [b][n][c]
__device__ bf16  g_k [BB * CN];      // [b][n][c]
__device__ bf16  g_v [BB * CN];      // channel-major [b][c][j]
__device__ float g_s [BB * SSTR];    // S[b][i][j] fp32 (pre-softmax)
__device__ bf16  g_p [BB * SSTR];    // P[b][i][j] bf16 (post-softmax)
__device__ bf16  g_o [BB * CN];      // [b][n][c]
__device__ bf16  g_w [4 * CC * CC];  // bf16 wq, wk, wv, wp

// ---------------------------------------------------------------------------
// Helpers
// ---------------------------------------------------------------------------
__device__ __forceinline__ uint32_t smem_u32(const void* p) {
    uint32_t a;
    asm("{ .reg .u64 t; cvta.to.shared.u64 t, %1; cvt.u32.u64 %0, t; }"
        : "=r"(a) : "l"(p));
    return a;
}

__device__ __forceinline__ uint32_t pack_bf2(float lo, float hi) {
    __nv_bfloat162 h = __floats2bfloat162_rn(lo, hi);
    return *(uint32_t*)&h;
}

#define CP_ASYNC16(saddr, gptr) \
    asm volatile("cp.async.cg.shared.global [%0], [%1], 16;" \
        :: "r"(saddr), "l"(gptr) : "memory")
#define CP_COMMIT() asm volatile("cp.async.commit_group;" ::: "memory")
#define CP_WAIT1()  asm volatile("cp.async.wait_group 1;" ::: "memory")
#define CP_WAIT0()  asm volatile("cp.async.wait_group 0;" ::: "memory")

#define LDMX4(r, addr) \
    asm volatile("ldmatrix.sync.aligned.m8n8.x4.shared.b16 {%0,%1,%2,%3}, [%4];" \
        : "=r"((r)[0]), "=r"((r)[1]), "=r"((r)[2]), "=r"((r)[3]) : "r"(addr))

// m16n8k16 bf16 MMA (sm_80 base ISA)
__device__ __forceinline__ void mma16n8k16(float d[4],
                                           const uint32_t a[4],
                                           const uint32_t b0, const uint32_t b1) {
    asm volatile(
        "mma.sync.aligned.m16n8k16.row.col.f32.bf16.bf16.f32 "
        "{%0,%1,%2,%3}, {%4,%5,%6,%7}, {%8,%9}, {%0,%1,%2,%3};"
        : "+f"(d[0]), "+f"(d[1]), "+f"(d[2]), "+f"(d[3])
        : "r"(a[0]), "r"(a[1]), "r"(a[2]), "r"(a[3]),
          "r"(b0), "r"(b1));
}

// ---------------------------------------------------------------------------
// Weight prep: fp32 wq/wk/wv/wp -> bf16 g_w
// ---------------------------------------------------------------------------
__global__ void __launch_bounds__(256)
prep_weights_kernel(const float* __restrict__ wq, const float* __restrict__ wk,
                    const float* __restrict__ wv, const float* __restrict__ wp,
                    bf16* __restrict__ wout)
{
    const int i = blockIdx.x * 256 + threadIdx.x;  // float4 index, 65536 per matrix
    const float4* src[4] = { (const float4*)wq, (const float4*)wk,
                             (const float4*)wv, (const float4*)wp };
#pragma unroll
    for (int m = 0; m < 4; m++) {
        float4 v = src[m][i];
        uint2 o;
        o.x = pack_bf2(v.x, v.y);
        o.y = pack_bf2(v.z, v.w);
        ((uint2*)(wout + m * CC * CC))[i] = o;
    }
}

// ---------------------------------------------------------------------------
// GroupNorm + transpose: x [b][c][n] fp32 -> xn token-major [b][n][c] bf16
// ---------------------------------------------------------------------------
__global__ void __launch_bounds__(256)
groupnorm_t_kernel(const float* __restrict__ x,
                   const float* __restrict__ gamma,
                   const float* __restrict__ beta,
                   bf16* __restrict__ xn)
{
    const int b = blockIdx.x / GG;
    const int g = blockIdx.x % GG;
    const size_t xbase = (size_t)b * CN + (size_t)g * CPG * NTOK;
    const int t = threadIdx.x;

    const float4* x4 = (const float4*)(x + xbase);
    const int M4 = (CPG * NTOK) / 4;   // 16384
    float s = 0.f, ss = 0.f;
    for (int i = t; i < M4; i += 256) {
        float4 v = x4[i];
        s  += v.x + v.y + v.z + v.w;
        ss += v.x*v.x + v.y*v.y + v.z*v.z + v.w*v.w;
    }
    __shared__ float rs[256], rq[256];
    rs[t] = s; rq[t] = ss;
    __syncthreads();
    for (int o = 128; o > 0; o >>= 1) {
        if (t < o) { rs[t] += rs[t+o]; rq[t] += rq[t+o]; }
        __syncthreads();
    }
    const float cnt  = (float)(CPG * NTOK);
    const float mean = rs[0] / cnt;
    const float var  = rq[0] / cnt - mean * mean;
    const float inv  = rsqrtf(var + EPSV);

    __shared__ float ts[64 * 65];
    const size_t obase = (size_t)b * CN + g * CPG;   // + n*CC + c
    for (int n0 = 0; n0 < NTOK; n0 += 64) {
        __syncthreads();
        for (int i = t; i < 64 * 16; i += 256) {
            const int c  = i >> 4;
            const int n4 = i & 15;
            const int cg = g * CPG + c;
            const float gm = gamma[cg] * inv;
            const float bt = beta[cg] - mean * gm;
            float4 v = *(const float4*)(x + (size_t)b * CN + (size_t)cg * NTOK + n0 + n4 * 4);
            ts[(n4*4 + 0) * 65 + c] = v.x * gm + bt;
            ts[(n4*4 + 1) * 65 + c] = v.y * gm + bt;
            ts[(n4*4 + 2) * 65 + c] = v.z * gm + bt;
            ts[(n4*4 + 3) * 65 + c] = v.w * gm + bt;
        }
        __syncthreads();
        for (int i = t; i < 64 * 16; i += 256) {
            const int n  = i >> 4;
            const int c4 = i & 15;
            uint2 o;
            o.x = pack_bf2(ts[n * 65 + c4*4 + 0], ts[n * 65 + c4*4 + 1]);
            o.y = pack_bf2(ts[n * 65 + c4*4 + 2], ts[n * 65 + c4*4 + 3]);
            *(uint2*)(xn + obase + (size_t)(n0 + n) * CC + c4 * 4) = o;
        }
    }
}

// ---------------------------------------------------------------------------
// Unified bf16 tensor-core GEMM, mma.sync m16n8k16 + ldmatrix + 3-stage pipe:
//   D[m][n] = alpha * sum_k A[m][k]*B[n][k]
//             (+ biasM[m]) (+ biasN[n]) (+ resid[m][n])
// A: [M x Ktot] bf16 K-contiguous. B: [N x Ktot] bf16 K-contiguous.
// D: fp32 (out_bf16=0) or bf16 (out_bf16=1), row stride ldc.
// CTA tile 128x128, BK=64, 8 warps (4x2), warp tile 32x64.
// ---------------------------------------------------------------------------
#define BKT 64
#define LDT 72                         // bf16 elems per smem row (144 B)
#define STG_ELEM (2 * 128 * LDT)       // A+B per stage (bf16 elems)
#define STG_BYTE (STG_ELEM * 2)

__global__ void __launch_bounds__(256)
gemm_bf(const bf16* __restrict__ Ag, const bf16* __restrict__ Bg,
        void* __restrict__ Dg, int Ktot, int ldc,
        long long sA, long long sB, long long sD,
        float alpha,
        const float* __restrict__ biasM, const float* __restrict__ biasN,
        const float* __restrict__ resid, int out_bf16)
{
    extern __shared__ bf16 sm[];

    const int tid  = threadIdx.x;
    const int lane = tid & 31;
    const int wid  = tid >> 5;
    const int wm   = (wid & 3) * 32;   // warp m offset in tile
    const int wn   = (wid >> 2) * 64;  // warp n offset in tile
    const int gtr  = lane >> 2;
    const int t4   = lane & 3;

    // ldmatrix per-lane addressing: lane -> (row-in-16, k-half)
    const int row16 = lane & 15;
    const int kh    = lane >> 4;       // 0 or 1

    const uint32_t smb = smem_u32(sm);
    // fragment base byte offsets within a stage (k0 added per k-step)
    const uint32_t aoff0 = (uint32_t)(((wm      + row16) * LDT + kh * 8) * 2);
    const uint32_t aoff1 = (uint32_t)(((wm + 16 + row16) * LDT + kh * 8) * 2);
    uint32_t boff[4];
#pragma unroll
    for (int p = 0; p < 4; ++p)
        boff[p] = (uint32_t)(((wn + p * 16 + row16) * LDT + kh * 8) * 2 + 128 * LDT * 2);

    const int bz = blockIdx.z;
    const bf16* A = Ag + (size_t)bz * sA;
    const bf16* B = Bg + (size_t)bz * sB;
    const int m0 = blockIdx.y * 128;
    const int n0 = blockIdx.x * 128;

    float acc[2][8][4];
#pragma unroll
    for (int i = 0; i < 2; i++)
#pragma unroll
        for (int j = 0; j < 8; j++)
#pragma unroll
            for (int q = 0; q < 4; q++) acc[i][j][q] = 0.f;

    const int NIT = Ktot / BKT;

    auto issue_loads = [&](int it, int stg) {
        const bf16* Asrc = A + (size_t)m0 * Ktot + it * BKT;
        const bf16* Bsrc = B + (size_t)n0 * Ktot + it * BKT;
        const uint32_t aB = smb + stg * STG_BYTE;
        const uint32_t bB = aB + 128 * LDT * 2;
#pragma unroll
        for (int r = 0; r < 4; r++) {
            const int idx = tid + r * 256;     // 0..1023
            const int row = idx >> 3;          // 0..127
            const int q   = idx & 7;           // 16B chunk within 64-elem row
            CP_ASYNC16(aB + (uint32_t)(row * LDT + q * 8) * 2u,
                       Asrc + (size_t)row * Ktot + q * 8);
            CP_ASYNC16(bB + (uint32_t)(row * LDT + q * 8) * 2u,
                       Bsrc + (size_t)row * Ktot + q * 8);
        }
        CP_COMMIT();
    };

    issue_loads(0, 0);
    if (NIT > 1) issue_loads(1, 1);

    for (int it = 0; it < NIT; ++it) {
        if (it + 1 < NIT) { CP_WAIT1(); } else { CP_WAIT0(); }
        __syncthreads();
        if (it + 2 < NIT) issue_loads(it + 2, (it + 2) % 3);

        const uint32_t sBase = smb + (it % 3) * STG_BYTE;
#pragma unroll
        for (int ks = 0; ks < 4; ++ks) {
            const uint32_t k0b = (uint32_t)(ks * 16 * 2);
            uint32_t af[2][4];
            LDMX4(af[0], sBase + aoff0 + k0b);
            LDMX4(af[1], sBase + aoff1 + k0b);
            uint32_t bfr[8][2];
#pragma unroll
            for (int p = 0; p < 4; ++p) {
                uint32_t rr[4];
                LDMX4(rr, sBase + boff[p] + k0b);
                bfr[2*p    ][0] = rr[0];
                bfr[2*p + 1][0] = rr[1];
                bfr[2*p    ][1] = rr[2];
                bfr[2*p + 1][1] = rr[3];
            }
#pragma unroll
            for (int ma = 0; ma < 2; ++ma)
#pragma unroll
                for (int nb = 0; nb < 8; ++nb)
                    mma16n8k16(acc[ma][nb], af[ma], bfr[nb][0], bfr[nb][1]);
        }
        // no second sync: next iteration's top sync protects stage reuse
    }

    // Epilogue: thread owns rows (wm+ma*16+gtr, +8), cols wn+nb*8+2*t4 (+1)
    const float* Rb = resid ? (resid + (size_t)bz * sD) : (const float*)0;
    float* Df = (float*)Dg + (size_t)bz * sD;
    bf16*  Dh = (bf16*)Dg + (size_t)bz * sD;
#pragma unroll
    for (int ma = 0; ma < 2; ++ma) {
        const int mrow0 = m0 + wm + ma * 16 + gtr;
        const int mrow1 = mrow0 + 8;
        const float bm0 = biasM ? biasM[mrow0] : 0.f;
        const float bm1 = biasM ? biasM[mrow1] : 0.f;
#pragma unroll
        for (int nb = 0; nb < 8; ++nb) {
            const int col = n0 + wn + nb * 8 + 2 * t4;
            float d0 = acc[ma][nb][0] * alpha + bm0;
            float d1 = acc[ma][nb][1] * alpha + bm0;
            float d2 = acc[ma][nb][2] * alpha + bm1;
            float d3 = acc[ma][nb][3] * alpha + bm1;
            if (biasN) {
                const float b0 = biasN[col], b1 = biasN[col + 1];
                d0 += b0; d1 += b1; d2 += b0; d3 += b1;
            }
            if (Rb) {
                const float2 r0 = *(const float2*)&Rb[(size_t)mrow0 * ldc + col];
                const float2 r1 = *(const float2*)&Rb[(size_t)mrow1 * ldc + col];
                d0 += r0.x; d1 += r0.y; d2 += r1.x; d3 += r1.y;
            }
            if (out_bf16) {
                *(uint32_t*)&Dh[(size_t)mrow0 * ldc + col] = pack_bf2(d0, d1);
                *(uint32_t*)&Dh[(size_t)mrow1 * ldc + col] = pack_bf2(d2, d3);
            } else {
                float2 o0 = { d0, d1 };
                float2 o1 = { d2, d3 };
                *(float2*)&Df[(size_t)mrow0 * ldc + col] = o0;
                *(float2*)&Df[(size_t)mrow1 * ldc + col] = o1;
            }
        }
    }
}

// ---------------------------------------------------------------------------
// Row softmax: one 256-thread block per row. fp32 S in, bf16 P out.
// ---------------------------------------------------------------------------
__global__ void __launch_bounds__(256)
softmax_rows(const float* __restrict__ S, bf16* __restrict__ P)
{
    const float4* R = (const float4*)(S + (size_t)blockIdx.x * NTOK);
    const int t = threadIdx.x;
    float4 v = R[t];

    float mx = fmaxf(fmaxf(v.x, v.y), fmaxf(v.z, v.w));
#pragma unroll
    for (int o = 16; o; o >>= 1) mx = fmaxf(mx, __shfl_xor_sync(0xffffffffu, mx, o));
    __shared__ float smax[8], ssum[8];
    if ((t & 31) == 0) smax[t >> 5] = mx;
    __syncthreads();
    float mm = smax[0];
#pragma unroll
    for (int i = 1; i < 8; ++i) mm = fmaxf(mm, smax[i]);

    float4 e;
    e.x = __expf(v.x - mm); e.y = __expf(v.y - mm);
    e.z = __expf(v.z - mm); e.w = __expf(v.w - mm);
    float su = e.x + e.y + e.z + e.w;
#pragma unroll
    for (int o = 16; o; o >>= 1) su += __shfl_xor_sync(0xffffffffu, su, o);
    if ((t & 31) == 0) ssum[t >> 5] = su;
    __syncthreads();
    float tot = 0.f;
#pragma unroll
    for (int i = 0; i < 8; ++i) tot += ssum[i];
    const float inv = 1.f / tot;

    uint2 o;
    o.x = pack_bf2(e.x * inv, e.y * inv);
    o.y = pack_bf2(e.z * inv, e.w * inv);
    *(uint2*)(P + (size_t)blockIdx.x * NTOK + t * 4) = o;
}

// ---------------------------------------------------------------------------
// Launcher
// ---------------------------------------------------------------------------
extern "C" void kernel_launch(void* const* d_in, const int* in_sizes, int n_in,
                              void* d_out, int out_size)
{
    const float* x     = (const float*)d_in[0];
    const float* gamma = (const float*)d_in[1];
    const float* beta  = (const float*)d_in[2];
    const float* wq    = (const float*)d_in[3];
    const float* bq    = (const float*)d_in[4];
    const float* wk    = (const float*)d_in[5];
    const float* bk    = (const float*)d_in[6];
    const float* wv    = (const float*)d_in[7];
    const float* bv    = (const float*)d_in[8];
    const float* wp    = (const float*)d_in[9];
    const float* bp    = (const float*)d_in[10];
    float* out = (float*)d_out;

    bf16 *xn, *q, *k, *v, *p, *o, *w;
    float *s;
    cudaGetSymbolAddress((void**)&xn, g_xn);
    cudaGetSymbolAddress((void**)&q,  g_q);
    cudaGetSymbolAddress((void**)&k,  g_k);
    cudaGetSymbolAddress((void**)&v,  g_v);
    cudaGetSymbolAddress((void**)&s,  g_s);
    cudaGetSymbolAddress((void**)&p,  g_p);
    cudaGetSymbolAddress((void**)&o,  g_o);
    cudaGetSymbolAddress((void**)&w,  g_w);
    const bf16* wrq = w + 0 * CC * CC;
    const bf16* wrk = w + 1 * CC * CC;
    const bf16* wrv = w + 2 * CC * CC;
    const bf16* wrp = w + 3 * CC * CC;

    const int SMEM_DYN = 3 * STG_BYTE;   // 110592 B
    cudaFuncSetAttribute(gemm_bf, cudaFuncAttributeMaxDynamicSharedMemorySize, SMEM_DYN);

    const float scale = 0.044194173824159216f;  // 1/sqrt(512)

    // 0) weights -> bf16
    prep_weights_kernel<<<256, 256>>>(wq, wk, wv, wp, w);

    // 1) GroupNorm -> token-major bf16 xn
    groupnorm_t_kernel<<<BB * GG, 256>>>(x, gamma, beta, xn);

    // 2) Q[n][o], K[n][o]:  M=1024(tokens) N=512(out-ch) K=512
    gemm_bf<<<dim3(4, 8, BB), 256, SMEM_DYN>>>(xn, wrq, q, CC, CC,
        (long long)CN, 0LL, (long long)CN, 1.f, 0, bq, 0, 1);
    gemm_bf<<<dim3(4, 8, BB), 256, SMEM_DYN>>>(xn, wrk, k, CC, CC,
        (long long)CN, 0LL, (long long)CN, 1.f, 0, bk, 0, 1);

    // 3) V[c][j]: M=512(ch) N=1024(tokens) K=512 (channel-major out)
    gemm_bf<<<dim3(8, 4, BB), 256, SMEM_DYN>>>(wrv, xn, v, CC, NTOK,
        0LL, (long long)CN, (long long)CN, 1.f, bv, 0, 0, 1);

    // 4) S[i][j] = scale * Q[i][:].K[j][:]  M=N=1024 K=512 (fp32 out)
    gemm_bf<<<dim3(8, 8, BB), 256, SMEM_DYN>>>(q, k, s, CC, NTOK,
        (long long)CN, (long long)CN, (long long)SSTR, scale, 0, 0, 0, 0);

    // 5) row softmax fp32 -> bf16 P
    softmax_rows<<<BB * NTOK, 256>>>(s, p);

    // 6) O[i][c] = P[i][:].V[c][:]  M=1024 N=512 K=1024
    gemm_bf<<<dim3(4, 8, BB), 256, SMEM_DYN>>>(p, v, o, NTOK, CC,
        (long long)SSTR, (long long)CN, (long long)CN, 1.f, 0, 0, 0, 1);

    // 7) out[c][n] = wp[c][:].O[n][:] + bp[c] + x[c][n]  M=512 N=1024 K=512 (fp32+resid)
    gemm_bf<<<dim3(8, 4, BB), 256, SMEM_DYN>>>(wrp, o, out, CC, NTOK,
        0LL, (long long)CN, (long long)CN, 1.f, bp, 0, x, 0);
}